// round 14
// baseline (speedup 1.0000x reference)
#include <cuda_runtime.h>
#include <cuda_fp16.h>
#include <math.h>
#include <stdint.h>

#define T_TOK 4096
#define H_DIM 1024
#define I_DIM 2816
#define N_EXP 8
#define MAXP  (T_TOK * 2)
#define NG1   (2 * I_DIM)      // 5632

// ---- tile config: block 128(M) x 256(N), warp tile 64x64, 8 warps ----
#define BM 128
#define BN 256
#define BKC 64                 // fp16 K elems per smem chunk (128 bytes/row)
#define A_TILE_BYTES (128 * 128)   // 16 KB
#define B_TILE_BYTES (256 * 128)   // 32 KB
#define OFF_A 0
#define OFF_B A_TILE_BYTES
#define STAGE_BYTES (A_TILE_BYTES + B_TILE_BYTES)   // 48 KB
#define NSTAGE 3
#define SMEM_DYN (NSTAGE * STAGE_BYTES)             // 144 KB, 1 CTA/SM

// ---------------- scratch ----------------
__device__ int   g_counts[N_EXP];
__device__ int   g_tokens[N_EXP][T_TOK];
__device__ float g_scales[N_EXP][T_TOK];
__device__ int   g_slot  [N_EXP][T_TOK];

__device__ __align__(16) __half g_x  [(size_t)T_TOK * H_DIM];
__device__ __align__(16) __half g_w31[(size_t)N_EXP * NG1 * H_DIM];
__device__ __align__(16) __half g_w2 [(size_t)N_EXP * H_DIM * I_DIM];
__device__ __align__(16) __half g_h  [(size_t)MAXP * I_DIM];
__device__ __align__(16) float  g_pair[(size_t)MAXP * H_DIM];

// ---------------- helpers ----------------
__device__ __forceinline__ uint32_t smem_u32(const void* p) {
    uint32_t a;
    asm("{ .reg .u64 t; cvta.to.shared.u64 t, %1; cvt.u32.u64 %0, t; }" : "=r"(a) : "l"(p));
    return a;
}
__device__ __forceinline__ void cp16(uint32_t dst, const void* src, uint32_t sz) {
    asm volatile("cp.async.cg.shared.global [%0], [%1], 16, %2;"
                 :: "r"(dst), "l"(src), "r"(sz) : "memory");
}
#define CP_COMMIT() asm volatile("cp.async.commit_group;" ::: "memory")
#define CP_WAIT0()  asm volatile("cp.async.wait_group 0;" ::: "memory")
#define CP_WAIT1()  asm volatile("cp.async.wait_group 1;" ::: "memory")
#define CP_WAIT2()  asm volatile("cp.async.wait_group 2;" ::: "memory")
#define LDSM_X4(r, addr) \
    asm volatile("ldmatrix.sync.aligned.m8n8.x4.shared.b16 {%0,%1,%2,%3}, [%4];" \
        : "=r"((r)[0]), "=r"((r)[1]), "=r"((r)[2]), "=r"((r)[3]) : "r"(addr))
__device__ __forceinline__ void mma16816(float* c, const uint32_t* a, uint32_t b0, uint32_t b1) {
    asm volatile("mma.sync.aligned.m16n8k16.row.col.f32.f16.f16.f32 "
        "{%0,%1,%2,%3}, {%4,%5,%6,%7}, {%8,%9}, {%0,%1,%2,%3};"
        : "+f"(c[0]), "+f"(c[1]), "+f"(c[2]), "+f"(c[3])
        : "r"(a[0]), "r"(a[1]), "r"(a[2]), "r"(a[3]), "r"(b0), "r"(b1));
}

// ---------------- small kernels ----------------
__global__ void zero_counts_kernel() {
    if (threadIdx.x < N_EXP) g_counts[threadIdx.x] = 0;
}

__global__ void router_kernel(const float* __restrict__ logits) {
    int t = blockIdx.x * blockDim.x + threadIdx.x;
    if (t >= T_TOK) return;
    float l[N_EXP];
    float mx = -1e30f;
#pragma unroll
    for (int e = 0; e < N_EXP; e++) { l[e] = logits[t * N_EXP + e]; mx = fmaxf(mx, l[e]); }
    float s = 0.f;
#pragma unroll
    for (int e = 0; e < N_EXP; e++) { l[e] = expf(l[e] - mx); s += l[e]; }
    float inv = 1.f / s;
    int e0 = 0;
#pragma unroll
    for (int e = 1; e < N_EXP; e++) if (l[e] > l[e0]) e0 = e;
    int e1 = (e0 == 0) ? 1 : 0;
#pragma unroll
    for (int e = 0; e < N_EXP; e++) if (e != e0 && l[e] > l[e1]) e1 = e;
    int p0 = atomicAdd(&g_counts[e0], 1);
    g_tokens[e0][p0] = t; g_scales[e0][p0] = l[e0] * inv; g_slot[e0][p0] = 2 * t;
    int p1 = atomicAdd(&g_counts[e1], 1);
    g_tokens[e1][p1] = t; g_scales[e1][p1] = l[e1] * inv; g_slot[e1][p1] = 2 * t + 1;
}

// one fused fp32->fp16 conversion over x, w31, w2 (streaming reads)
#define N4X  (T_TOK * H_DIM / 4)
#define N4W1 ((int)(((size_t)N_EXP * NG1 * H_DIM) / 4))
#define N4W2 ((int)(((size_t)N_EXP * H_DIM * I_DIM) / 4))
__global__ void cvt_all_kernel(const float* __restrict__ x,
                               const float* __restrict__ w31,
                               const float* __restrict__ w2) {
    int i = blockIdx.x * blockDim.x + threadIdx.x;
    const float* src;
    __half* dst;
    int j = i;
    if (j < N4X) { src = x; dst = g_x; }
    else if ((j -= N4X) < N4W1) { src = w31; dst = g_w31; }
    else if ((j -= N4W1) < N4W2) { src = w2; dst = g_w2; }
    else return;
    float4 v = __ldcs(((const float4*)src) + j);
    __half2 a; a.x = __float2half_rn(v.x); a.y = __float2half_rn(v.y);
    __half2 b; b.x = __float2half_rn(v.z); b.y = __float2half_rn(v.w);
    ((__half2*)dst)[2 * j] = a;
    ((__half2*)dst)[2 * j + 1] = b;
}

// ---------------- grouped fp16 mma.sync GEMM (128x256 block, 64x64 warp) ----
// MODE 0: GEMM1+SwiGLU. A = x (gather token). B tile rows interleaved:
//         even = w3(u) col, odd = w1(g) col. Epilogue silu(g)*u -> fp16 h.
//         Block covers 128 h-cols. K=1024.
// MODE 1: GEMM2. A = h (gather slot), B = w2, writes g_pair with routing
//         scale. Block covers 256 out-cols. K=2816.
template <int MODE>
__global__ __launch_bounds__(256, 1) void moe_gemm_kernel() {
    constexpr int K      = (MODE == 0) ? H_DIM : I_DIM;
    constexpr int CHUNKS = K / BKC;

    int e   = blockIdx.z;
    int cnt = g_counts[e];
    int m0  = blockIdx.y * BM;
    if (m0 >= cnt) return;

    const __half* A = (MODE == 0) ? g_x : g_h;
    const __half* B = (MODE == 0) ? g_w31 + (size_t)e * NG1 * H_DIM
                                  : g_w2  + (size_t)e * H_DIM * I_DIM;
    const int* idxA = (MODE == 0) ? &g_tokens[e][0] : &g_slot[e][0];

    extern __shared__ char smem[];
    uint32_t sbase = smem_u32(smem);
    int tid  = threadIdx.x;
    int lane = tid & 31;
    int wid  = tid >> 5;
    int wm   = (wid & 1) * 64;      // warp M offset (2 along M)
    int wn   = (wid >> 1) * 64;     // warp N offset (4 along N, B-row space)

    // ---- loader mapping: thread -> rows row0+32r, 16B-unit col16 ----
    int col16 = tid & 7;
    int row0  = tid >> 3;
    uint32_t swA[4], swB[8];
    const __half *aP[4], *bP[8];
    uint32_t asz[4];
#pragma unroll
    for (int r = 0; r < 4; r++) {
        int rt = row0 + 32 * r;
        uint32_t off = rt * 128 + col16 * 16;
        swA[r] = off ^ ((off >> 3) & 0x70);
        int mrow = m0 + rt;
        if (mrow < cnt) {
            size_t rg = (size_t)idxA[mrow];
            aP[r] = A + rg * K + col16 * 8;
            asz[r] = 16;
        } else {
            aP[r] = A; asz[r] = 0;   // zero-fill
        }
    }
#pragma unroll
    for (int r = 0; r < 8; r++) {
        int rt = row0 + 32 * r;                       // 0..255
        uint32_t off = rt * 128 + col16 * 16;
        swB[r] = off ^ ((off >> 3) & 0x70);
        size_t brow;
        if (MODE == 0) {
            int lc = blockIdx.x * 128 + (rt >> 1);                 // logical h col
            brow = (rt & 1) ? (size_t)(I_DIM + lc) : (size_t)lc;   // odd=w1(g), even=w3(u)
        } else {
            brow = (size_t)(blockIdx.x * BN + rt);
        }
        bP[r] = B + brow * K + col16 * 8;
    }

    auto prefetch = [&](int c, int stg) {
        uint32_t st = sbase + (uint32_t)stg * STAGE_BYTES;
        int k0 = c * BKC;
#pragma unroll
        for (int r = 0; r < 4; r++)
            cp16(st + OFF_A + swA[r], aP[r] + k0, asz[r]);
#pragma unroll
        for (int r = 0; r < 8; r++)
            cp16(st + OFF_B + swB[r], bP[r] + k0, 16);
        CP_COMMIT();
    };

    // ---- ldmatrix address precompute ----
    int kh = lane >> 4;
    uint32_t rowOffA[4], rxA[4];
#pragma unroll
    for (int mi = 0; mi < 4; mi++) {
        int ra = wm + mi * 16 + (lane & 15);
        rowOffA[mi] = (uint32_t)ra * 128;
        rxA[mi] = ra & 7;
    }
    uint32_t rowOffB[4], rxB[4];
#pragma unroll
    for (int g = 0; g < 4; g++) {
        int rb = wn + g * 16 + (lane & 15);
        rowOffB[g] = (uint32_t)rb * 128;
        rxB[g] = rb & 7;
    }

    float acc[4][8][4] = {};   // [mi][g*2+s][4]

    prefetch(0, 0);
    if (CHUNKS > 1) prefetch(1, 1);
    if (CHUNKS > 2) prefetch(2, 2);

    int stg = 0;
    for (int c = 0; c < CHUNKS; c++) {
        int rem = CHUNKS - 1 - c;
        if (rem >= 2) { CP_WAIT2(); } else if (rem == 1) { CP_WAIT1(); } else { CP_WAIT0(); }
        __syncthreads();
        uint32_t st = sbase + (uint32_t)stg * STAGE_BYTES;

#pragma unroll
        for (int ks = 0; ks < 4; ks++) {
            uint32_t ub = (uint32_t)(ks * 2 + kh);
            uint32_t af[4][4], bf[4][4];
#pragma unroll
            for (int g = 0; g < 4; g++)
                LDSM_X4(bf[g], st + OFF_B + rowOffB[g] + ((ub ^ rxB[g]) << 4));
#pragma unroll
            for (int mi = 0; mi < 4; mi++)
                LDSM_X4(af[mi], st + OFF_A + rowOffA[mi] + ((ub ^ rxA[mi]) << 4));
            // 32 independent MMAs
#pragma unroll
            for (int mi = 0; mi < 4; mi++)
#pragma unroll
                for (int g = 0; g < 4; g++)
#pragma unroll
                    for (int s = 0; s < 2; s++)
                        mma16816(acc[mi][g * 2 + s], af[mi], bf[g][0 + s], bf[g][2 + s]);
        }
        __syncthreads();
        if (c + 3 < CHUNKS) prefetch(c + 3, stg);   // reuse just-freed stage
        stg++; if (stg >= NSTAGE) stg = 0;
    }

    // ---- epilogue ----
#pragma unroll
    for (int mi = 0; mi < 4; mi++) {
        int r0 = m0 + wm + mi * 16 + (lane >> 2);
        int r1 = r0 + 8;
        bool v0 = r0 < cnt, v1 = r1 < cnt;
        int  s0 = v0 ? g_slot[e][r0] : 0;
        int  s1 = v1 ? g_slot[e][r1] : 0;
        if (MODE == 0) {
            // acc[mi][j]: c0=u(r0), c1=g(r0), c2=u(r1), c3=g(r1) for h col hc
#pragma unroll
            for (int j = 0; j < 8; j++) {
                int hc = blockIdx.x * 128 + (wn >> 1) + j * 4 + (lane & 3);
                if (v0) {
                    float gg = acc[mi][j][1];
                    float hv = acc[mi][j][0] * (gg / (1.f + __expf(-gg)));
                    g_h[(size_t)s0 * I_DIM + hc] = __float2half_rn(hv);
                }
                if (v1) {
                    float gg = acc[mi][j][3];
                    float hv = acc[mi][j][2] * (gg / (1.f + __expf(-gg)));
                    g_h[(size_t)s1 * I_DIM + hc] = __float2half_rn(hv);
                }
            }
        } else {
            float sc0 = v0 ? g_scales[e][r0] : 0.f;
            float sc1 = v1 ? g_scales[e][r1] : 0.f;
            float* p0 = g_pair + (size_t)s0 * H_DIM;
            float* p1 = g_pair + (size_t)s1 * H_DIM;
#pragma unroll
            for (int j = 0; j < 8; j++) {
                int cc = blockIdx.x * BN + wn + j * 8 + (lane & 3) * 2;
                if (v0) {
                    float2 w = make_float2(acc[mi][j][0] * sc0, acc[mi][j][1] * sc0);
                    *(float2*)(p0 + cc) = w;
                }
                if (v1) {
                    float2 w = make_float2(acc[mi][j][2] * sc1, acc[mi][j][3] * sc1);
                    *(float2*)(p1 + cc) = w;
                }
            }
        }
    }
}

// out[t] = pair[2t] + pair[2t+1]
__global__ void combine_kernel(float* __restrict__ out) {
    int idx = blockIdx.x * blockDim.x + threadIdx.x;
    const int HV = H_DIM / 4;
    if (idx >= T_TOK * HV) return;
    int t = idx / HV;
    int c = idx - t * HV;
    const float4* p = (const float4*)g_pair;
    float4 a = p[(size_t)(2 * t) * HV + c];
    float4 b = p[(size_t)(2 * t + 1) * HV + c];
    ((float4*)out)[idx] = make_float4(a.x + b.x, a.y + b.y, a.z + b.z, a.w + b.w);
}

extern "C" void kernel_launch(void* const* d_in, const int* in_sizes, int n_in,
                              void* d_out, int out_size) {
    const float* x      = (const float*)d_in[0];
    const float* logits = (const float*)d_in[1];
    const float* w3w1   = (const float*)d_in[2];
    const float* w2     = (const float*)d_in[3];
    float* out = (float*)d_out;

    cudaFuncSetAttribute(moe_gemm_kernel<0>, cudaFuncAttributeMaxDynamicSharedMemorySize, SMEM_DYN);
    cudaFuncSetAttribute(moe_gemm_kernel<1>, cudaFuncAttributeMaxDynamicSharedMemorySize, SMEM_DYN);

    zero_counts_kernel<<<1, 32>>>();
    router_kernel<<<(T_TOK + 255) / 256, 256>>>(logits);

    int n4tot = N4X + N4W1 + N4W2;
    cvt_all_kernel<<<(n4tot + 255) / 256, 256>>>(x, w3w1, w2);

    dim3 blk(256);
    dim3 g1(I_DIM / 128, T_TOK / BM, N_EXP);  // 22 x 32 x 8 (128 h-cols per block)
    moe_gemm_kernel<0><<<g1, blk, SMEM_DYN>>>();

    dim3 g2(H_DIM / BN, T_TOK / BM, N_EXP);   // 4 x 32 x 8
    moe_gemm_kernel<1><<<g2, blk, SMEM_DYN>>>();

    combine_kernel<<<(T_TOK * (H_DIM / 4) + 255) / 256, 256>>>(out);
}

// round 15
// speedup vs baseline: 1.0580x; 1.0580x over previous
#include <cuda_runtime.h>
#include <cuda_fp16.h>
#include <math.h>
#include <stdint.h>

#define T_TOK 4096
#define H_DIM 1024
#define I_DIM 2816
#define N_EXP 8
#define MAXP  (T_TOK * 2)
#define NG1   (2 * I_DIM)      // 5632

// ---- tile config: block 128x128 per pass, 2 passes per block, warp 64x32 ----
#define BM 128
#define BKC 64                 // fp16 K elems per smem chunk (128 bytes/row)
#define TILE_BYTES (128 * 128)
#define OFF_A 0
#define OFF_B TILE_BYTES
#define STAGE_BYTES (2 * TILE_BYTES)       // 32 KB
#define NSTAGE 3
#define SMEM_DYN (NSTAGE * STAGE_BYTES)    // 96 KB -> 2 CTAs/SM

// ---------------- scratch ----------------
__device__ int   g_counts[N_EXP];
__device__ int   g_tokens[N_EXP][T_TOK];
__device__ float g_scales[N_EXP][T_TOK];
__device__ int   g_slot  [N_EXP][T_TOK];

__device__ __align__(16) __half g_x  [(size_t)T_TOK * H_DIM];
__device__ __align__(16) __half g_w31[(size_t)N_EXP * NG1 * H_DIM];
__device__ __align__(16) __half g_w2 [(size_t)N_EXP * H_DIM * I_DIM];
__device__ __align__(16) __half g_h  [(size_t)MAXP * I_DIM];
__device__ __align__(16) float  g_pair[(size_t)MAXP * H_DIM];

// ---------------- helpers ----------------
__device__ __forceinline__ uint32_t smem_u32(const void* p) {
    uint32_t a;
    asm("{ .reg .u64 t; cvta.to.shared.u64 t, %1; cvt.u32.u64 %0, t; }" : "=r"(a) : "l"(p));
    return a;
}
__device__ __forceinline__ void cp16(uint32_t dst, const void* src, uint32_t sz) {
    asm volatile("cp.async.cg.shared.global [%0], [%1], 16, %2;"
                 :: "r"(dst), "l"(src), "r"(sz) : "memory");
}
#define CP_COMMIT() asm volatile("cp.async.commit_group;" ::: "memory")
#define CP_WAIT0()  asm volatile("cp.async.wait_group 0;" ::: "memory")
#define CP_WAIT1()  asm volatile("cp.async.wait_group 1;" ::: "memory")
#define CP_WAIT2()  asm volatile("cp.async.wait_group 2;" ::: "memory")
#define LDSM_X4(r, addr) \
    asm volatile("ldmatrix.sync.aligned.m8n8.x4.shared.b16 {%0,%1,%2,%3}, [%4];" \
        : "=r"((r)[0]), "=r"((r)[1]), "=r"((r)[2]), "=r"((r)[3]) : "r"(addr))
__device__ __forceinline__ void mma16816(float* c, const uint32_t* a, uint32_t b0, uint32_t b1) {
    asm volatile("mma.sync.aligned.m16n8k16.row.col.f32.f16.f16.f32 "
        "{%0,%1,%2,%3}, {%4,%5,%6,%7}, {%8,%9}, {%0,%1,%2,%3};"
        : "+f"(c[0]), "+f"(c[1]), "+f"(c[2]), "+f"(c[3])
        : "r"(a[0]), "r"(a[1]), "r"(a[2]), "r"(a[3]), "r"(b0), "r"(b1));
}

// ---------------- small kernels ----------------
__global__ void zero_counts_kernel() {
    if (threadIdx.x < N_EXP) g_counts[threadIdx.x] = 0;
}

__global__ void router_kernel(const float* __restrict__ logits) {
    int t = blockIdx.x * blockDim.x + threadIdx.x;
    if (t >= T_TOK) return;
    float l[N_EXP];
    float mx = -1e30f;
#pragma unroll
    for (int e = 0; e < N_EXP; e++) { l[e] = logits[t * N_EXP + e]; mx = fmaxf(mx, l[e]); }
    float s = 0.f;
#pragma unroll
    for (int e = 0; e < N_EXP; e++) { l[e] = expf(l[e] - mx); s += l[e]; }
    float inv = 1.f / s;
    int e0 = 0;
#pragma unroll
    for (int e = 1; e < N_EXP; e++) if (l[e] > l[e0]) e0 = e;
    int e1 = (e0 == 0) ? 1 : 0;
#pragma unroll
    for (int e = 0; e < N_EXP; e++) if (e != e0 && l[e] > l[e1]) e1 = e;
    int p0 = atomicAdd(&g_counts[e0], 1);
    g_tokens[e0][p0] = t; g_scales[e0][p0] = l[e0] * inv; g_slot[e0][p0] = 2 * t;
    int p1 = atomicAdd(&g_counts[e1], 1);
    g_tokens[e1][p1] = t; g_scales[e1][p1] = l[e1] * inv; g_slot[e1][p1] = 2 * t + 1;
}

// one fused fp32->fp16 conversion over x, w31, w2 (streaming reads)
#define N4X  (T_TOK * H_DIM / 4)
#define N4W1 ((int)(((size_t)N_EXP * NG1 * H_DIM) / 4))
#define N4W2 ((int)(((size_t)N_EXP * H_DIM * I_DIM) / 4))
__global__ void cvt_all_kernel(const float* __restrict__ x,
                               const float* __restrict__ w31,
                               const float* __restrict__ w2) {
    int i = blockIdx.x * blockDim.x + threadIdx.x;
    const float* src;
    __half* dst;
    int j = i;
    if (j < N4X) { src = x; dst = g_x; }
    else if ((j -= N4X) < N4W1) { src = w31; dst = g_w31; }
    else if ((j -= N4W1) < N4W2) { src = w2; dst = g_w2; }
    else return;
    float4 v = __ldcs(((const float4*)src) + j);
    __half2 a; a.x = __float2half_rn(v.x); a.y = __float2half_rn(v.y);
    __half2 b; b.x = __float2half_rn(v.z); b.y = __float2half_rn(v.w);
    ((__half2*)dst)[2 * j] = a;
    ((__half2*)dst)[2 * j + 1] = b;
}

// ---------------- grouped fp16 mma.sync GEMM, 2 N-tiles per block ----------------
// Each block runs a continuous 2*CHUNKS chunk stream: pass 0 = first N-tile,
// pass 1 = second N-tile (B pointer advanced); A identical both passes (L2 hit).
// Pipeline never drains at the pass boundary; epilogue(0) overlaps the loads
// of pass 1's first chunks.
// MODE 0: GEMM1+SwiGLU. A = x (gather token). B rows interleaved even=w3(u),
//         odd=w1(g). Epilogue silu(g)*u -> fp16 h. Block covers 128 h-cols
//         (64 per pass). K=1024.
// MODE 1: GEMM2. A = h (gather slot), B = w2, writes g_pair with routing
//         scale. Block covers 256 out-cols (128 per pass). K=2816.
template <int MODE>
__global__ __launch_bounds__(256, 2) void moe_gemm_kernel() {
    constexpr int K      = (MODE == 0) ? H_DIM : I_DIM;
    constexpr int CHUNKS = K / BKC;
    constexpr int TC     = 2 * CHUNKS;                  // two passes
    constexpr int BDELTA = ((MODE == 0) ? 64 : 128) * K; // B advance for pass 1

    int e   = blockIdx.z;
    int cnt = g_counts[e];
    int m0  = blockIdx.y * BM;
    if (m0 >= cnt) return;

    const __half* A = (MODE == 0) ? g_x : g_h;
    const __half* B = (MODE == 0) ? g_w31 + (size_t)e * NG1 * H_DIM
                                  : g_w2  + (size_t)e * H_DIM * I_DIM;
    const int* idxA = (MODE == 0) ? &g_tokens[e][0] : &g_slot[e][0];

    extern __shared__ char smem[];
    uint32_t sbase = smem_u32(smem);
    int tid  = threadIdx.x;
    int lane = tid & 31;
    int wid  = tid >> 5;
    int wm   = (wid & 1) * 64;      // warp M offset
    int wn   = (wid >> 1) * 32;     // warp N offset (B-row space)

    // ---- loader mapping: thread -> rows row0+32r, 16B-unit col16 ----
    int col16 = tid & 7;
    int row0  = tid >> 3;
    uint32_t sw[4];
    const __half *aP[4], *bP[4];
    uint32_t asz[4];
#pragma unroll
    for (int r = 0; r < 4; r++) {
        int rt = row0 + 32 * r;
        uint32_t off = rt * 128 + col16 * 16;
        sw[r] = off ^ ((off >> 3) & 0x70);
        int mrow = m0 + rt;
        if (mrow < cnt) {
            size_t rg = (size_t)idxA[mrow];
            aP[r] = A + rg * K + col16 * 8;
            asz[r] = 16;
        } else {
            aP[r] = A; asz[r] = 0;   // zero-fill
        }
        size_t brow;
        if (MODE == 0) {
            int lc = blockIdx.x * 128 + (rt >> 1);                 // pass-0 h col
            brow = (rt & 1) ? (size_t)(I_DIM + lc) : (size_t)lc;   // odd=w1(g), even=w3(u)
        } else {
            brow = (size_t)(blockIdx.x * 256 + rt);
        }
        bP[r] = B + brow * K + col16 * 8;
    }

    auto prefetch = [&](int c, int stg) {
        uint32_t st = sbase + (uint32_t)stg * STAGE_BYTES;
        int cc = (c < CHUNKS) ? c : (c - CHUNKS);
        int k0 = cc * BKC;
        int boff = (c < CHUNKS) ? 0 : BDELTA;
#pragma unroll
        for (int r = 0; r < 4; r++) {
            cp16(st + OFF_A + sw[r], aP[r] + k0, asz[r]);
            cp16(st + OFF_B + sw[r], bP[r] + boff + k0, 16);
        }
        CP_COMMIT();
    };

    // ---- ldmatrix address precompute ----
    int kh = lane >> 4;
    uint32_t rowOffA[4], rxA[4];
#pragma unroll
    for (int mi = 0; mi < 4; mi++) {
        int ra = wm + mi * 16 + (lane & 15);
        rowOffA[mi] = (uint32_t)ra * 128;
        rxA[mi] = ra & 7;
    }
    uint32_t rowOffB[2], rxB[2];
#pragma unroll
    for (int g = 0; g < 2; g++) {
        int rb = wn + g * 16 + (lane & 15);
        rowOffB[g] = (uint32_t)rb * 128;
        rxB[g] = rb & 7;
    }

    float acc[4][4][4] = {};   // [mi][g*2+s][4]

    auto epilogue = [&](int pass) {
#pragma unroll
        for (int mi = 0; mi < 4; mi++) {
            int r0 = m0 + wm + mi * 16 + (lane >> 2);
            int r1 = r0 + 8;
            bool v0 = r0 < cnt, v1 = r1 < cnt;
            int  s0 = v0 ? g_slot[e][r0] : 0;
            int  s1 = v1 ? g_slot[e][r1] : 0;
            if (MODE == 0) {
#pragma unroll
                for (int j = 0; j < 4; j++) {
                    int hc = blockIdx.x * 128 + pass * 64 + (wn >> 1) + j * 4 + (lane & 3);
                    if (v0) {
                        float gg = acc[mi][j][1];
                        float hv = acc[mi][j][0] * (gg / (1.f + __expf(-gg)));
                        g_h[(size_t)s0 * I_DIM + hc] = __float2half_rn(hv);
                    }
                    if (v1) {
                        float gg = acc[mi][j][3];
                        float hv = acc[mi][j][2] * (gg / (1.f + __expf(-gg)));
                        g_h[(size_t)s1 * I_DIM + hc] = __float2half_rn(hv);
                    }
                }
            } else {
                float sc0 = v0 ? g_scales[e][r0] : 0.f;
                float sc1 = v1 ? g_scales[e][r1] : 0.f;
                float* p0 = g_pair + (size_t)s0 * H_DIM;
                float* p1 = g_pair + (size_t)s1 * H_DIM;
#pragma unroll
                for (int j = 0; j < 4; j++) {
                    int cc = blockIdx.x * 256 + pass * 128 + wn + j * 8 + (lane & 3) * 2;
                    if (v0) {
                        float2 w = make_float2(acc[mi][j][0] * sc0, acc[mi][j][1] * sc0);
                        *(float2*)(p0 + cc) = w;
                    }
                    if (v1) {
                        float2 w = make_float2(acc[mi][j][2] * sc1, acc[mi][j][3] * sc1);
                        *(float2*)(p1 + cc) = w;
                    }
                }
            }
        }
    };

    prefetch(0, 0);
    prefetch(1, 1);
    prefetch(2, 2);

    int stg = 0;
    for (int c = 0; c < TC; c++) {
        int rem = TC - 1 - c;
        if (rem >= 2) { CP_WAIT2(); } else if (rem == 1) { CP_WAIT1(); } else { CP_WAIT0(); }
        __syncthreads();
        uint32_t st = sbase + (uint32_t)stg * STAGE_BYTES;

#pragma unroll
        for (int ks = 0; ks < 4; ks++) {
            uint32_t ub = (uint32_t)(ks * 2 + kh);
            uint32_t af[4][4], bf[2][4];
#pragma unroll
            for (int g = 0; g < 2; g++)
                LDSM_X4(bf[g], st + OFF_B + rowOffB[g] + ((ub ^ rxB[g]) << 4));
#pragma unroll
            for (int mi = 0; mi < 4; mi++)
                LDSM_X4(af[mi], st + OFF_A + rowOffA[mi] + ((ub ^ rxA[mi]) << 4));
            // 16 independent MMAs
#pragma unroll
            for (int mi = 0; mi < 4; mi++)
#pragma unroll
                for (int g = 0; g < 2; g++)
#pragma unroll
                    for (int s = 0; s < 2; s++)
                        mma16816(acc[mi][g * 2 + s], af[mi], bf[g][0 + s], bf[g][2 + s]);
        }
        __syncthreads();                 // all warps done reading this stage
        if (c + 3 < TC) prefetch(c + 3, stg);   // reuse just-freed stage
        if (c == CHUNKS - 1) {
            epilogue(0);                 // pass-1 loads already in flight
#pragma unroll
            for (int mi = 0; mi < 4; mi++)
#pragma unroll
                for (int j = 0; j < 4; j++)
#pragma unroll
                    for (int q = 0; q < 4; q++)
                        acc[mi][j][q] = 0.f;
        }
        stg++; if (stg >= NSTAGE) stg = 0;
    }

    epilogue(1);
}

// out[t] = pair[2t] + pair[2t+1]
__global__ void combine_kernel(float* __restrict__ out) {
    int idx = blockIdx.x * blockDim.x + threadIdx.x;
    const int HV = H_DIM / 4;
    if (idx >= T_TOK * HV) return;
    int t = idx / HV;
    int c = idx - t * HV;
    const float4* p = (const float4*)g_pair;
    float4 a = p[(size_t)(2 * t) * HV + c];
    float4 b = p[(size_t)(2 * t + 1) * HV + c];
    ((float4*)out)[idx] = make_float4(a.x + b.x, a.y + b.y, a.z + b.z, a.w + b.w);
}

extern "C" void kernel_launch(void* const* d_in, const int* in_sizes, int n_in,
                              void* d_out, int out_size) {
    const float* x      = (const float*)d_in[0];
    const float* logits = (const float*)d_in[1];
    const float* w3w1   = (const float*)d_in[2];
    const float* w2     = (const float*)d_in[3];
    float* out = (float*)d_out;

    cudaFuncSetAttribute(moe_gemm_kernel<0>, cudaFuncAttributeMaxDynamicSharedMemorySize, SMEM_DYN);
    cudaFuncSetAttribute(moe_gemm_kernel<1>, cudaFuncAttributeMaxDynamicSharedMemorySize, SMEM_DYN);

    zero_counts_kernel<<<1, 32>>>();
    router_kernel<<<(T_TOK + 255) / 256, 256>>>(logits);

    int n4tot = N4X + N4W1 + N4W2;
    cvt_all_kernel<<<(n4tot + 255) / 256, 256>>>(x, w3w1, w2);

    dim3 blk(256);
    dim3 g1(I_DIM / 128, T_TOK / BM, N_EXP);  // 22 x 32 x 8 (128 h-cols per block, 2 passes)
    moe_gemm_kernel<0><<<g1, blk, SMEM_DYN>>>();

    dim3 g2(H_DIM / 256, T_TOK / BM, N_EXP);  // 4 x 32 x 8 (256 cols per block, 2 passes)
    moe_gemm_kernel<1><<<g2, blk, SMEM_DYN>>>();

    combine_kernel<<<(T_TOK * (H_DIM / 4) + 255) / 256, 256>>>(out);
}

// round 16
// speedup vs baseline: 1.1285x; 1.0666x over previous
#include <cuda_runtime.h>
#include <cuda_fp16.h>
#include <math.h>
#include <stdint.h>

#define T_TOK 4096
#define H_DIM 1024
#define I_DIM 2816
#define N_EXP 8
#define MAXP  (T_TOK * 2)
#define NG1   (2 * I_DIM)      // 5632

// ---- tile config (R12-proven): block 128x128, warp 64x32, 2 CTAs/SM ----
#define BM 128
#define BKC 64                 // fp16 K elems per smem chunk (128 bytes/row)
#define TILE_BYTES (128 * 128)
#define OFF_A 0
#define OFF_B TILE_BYTES
#define STAGE_BYTES (2 * TILE_BYTES)       // 32 KB
#define NSTAGE 3
#define SMEM_DYN (NSTAGE * STAGE_BYTES)    // 96 KB -> 2 CTAs/SM

// ---------------- scratch ----------------
__device__ int   g_counts[N_EXP];
__device__ int   g_tokens[N_EXP][T_TOK];
__device__ float g_scales[N_EXP][T_TOK];
__device__ int   g_slot  [N_EXP][T_TOK];

__device__ __align__(16) __half g_x  [(size_t)T_TOK * H_DIM];
__device__ __align__(16) __half g_w31[(size_t)N_EXP * NG1 * H_DIM];
__device__ __align__(16) __half g_w2 [(size_t)N_EXP * H_DIM * I_DIM];
__device__ __align__(16) __half g_h  [(size_t)MAXP * I_DIM];
__device__ __align__(16) float  g_pair[(size_t)MAXP * H_DIM];

// ---------------- helpers ----------------
__device__ __forceinline__ uint32_t smem_u32(const void* p) {
    uint32_t a;
    asm("{ .reg .u64 t; cvta.to.shared.u64 t, %1; cvt.u32.u64 %0, t; }" : "=r"(a) : "l"(p));
    return a;
}
__device__ __forceinline__ void cp16(uint32_t dst, const void* src, uint32_t sz) {
    asm volatile("cp.async.cg.shared.global [%0], [%1], 16, %2;"
                 :: "r"(dst), "l"(src), "r"(sz) : "memory");
}
#define CP_COMMIT() asm volatile("cp.async.commit_group;" ::: "memory")
#define CP_WAIT0()  asm volatile("cp.async.wait_group 0;" ::: "memory")
#define CP_WAIT1()  asm volatile("cp.async.wait_group 1;" ::: "memory")
#define LDSM_X4(r, addr) \
    asm volatile("ldmatrix.sync.aligned.m8n8.x4.shared.b16 {%0,%1,%2,%3}, [%4];" \
        : "=r"((r)[0]), "=r"((r)[1]), "=r"((r)[2]), "=r"((r)[3]) : "r"(addr))
__device__ __forceinline__ void mma16816(float* c, const uint32_t* a, uint32_t b0, uint32_t b1) {
    asm volatile("mma.sync.aligned.m16n8k16.row.col.f32.f16.f16.f32 "
        "{%0,%1,%2,%3}, {%4,%5,%6,%7}, {%8,%9}, {%0,%1,%2,%3};"
        : "+f"(c[0]), "+f"(c[1]), "+f"(c[2]), "+f"(c[3])
        : "r"(a[0]), "r"(a[1]), "r"(a[2]), "r"(a[3]), "r"(b0), "r"(b1));
}

// ---------------- small kernels ----------------
__global__ void zero_counts_kernel() {
    if (threadIdx.x < N_EXP) g_counts[threadIdx.x] = 0;
}

__global__ void router_kernel(const float* __restrict__ logits) {
    int t = blockIdx.x * blockDim.x + threadIdx.x;
    if (t >= T_TOK) return;
    float l[N_EXP];
    float mx = -1e30f;
#pragma unroll
    for (int e = 0; e < N_EXP; e++) { l[e] = logits[t * N_EXP + e]; mx = fmaxf(mx, l[e]); }
    float s = 0.f;
#pragma unroll
    for (int e = 0; e < N_EXP; e++) { l[e] = expf(l[e] - mx); s += l[e]; }
    float inv = 1.f / s;
    int e0 = 0;
#pragma unroll
    for (int e = 1; e < N_EXP; e++) if (l[e] > l[e0]) e0 = e;
    int e1 = (e0 == 0) ? 1 : 0;
#pragma unroll
    for (int e = 0; e < N_EXP; e++) if (e != e0 && l[e] > l[e1]) e1 = e;
    int p0 = atomicAdd(&g_counts[e0], 1);
    g_tokens[e0][p0] = t; g_scales[e0][p0] = l[e0] * inv; g_slot[e0][p0] = 2 * t;
    int p1 = atomicAdd(&g_counts[e1], 1);
    g_tokens[e1][p1] = t; g_scales[e1][p1] = l[e1] * inv; g_slot[e1][p1] = 2 * t + 1;
}

// one fused fp32->fp16 conversion over x, w31, w2 (streaming reads)
#define N4X  (T_TOK * H_DIM / 4)
#define N4W1 ((int)(((size_t)N_EXP * NG1 * H_DIM) / 4))
#define N4W2 ((int)(((size_t)N_EXP * H_DIM * I_DIM) / 4))
__global__ void cvt_all_kernel(const float* __restrict__ x,
                               const float* __restrict__ w31,
                               const float* __restrict__ w2) {
    int i = blockIdx.x * blockDim.x + threadIdx.x;
    const float* src;
    __half* dst;
    int j = i;
    if (j < N4X) { src = x; dst = g_x; }
    else if ((j -= N4X) < N4W1) { src = w31; dst = g_w31; }
    else if ((j -= N4W1) < N4W2) { src = w2; dst = g_w2; }
    else return;
    float4 v = __ldcs(((const float4*)src) + j);
    __half2 a; a.x = __float2half_rn(v.x); a.y = __float2half_rn(v.y);
    __half2 b; b.x = __float2half_rn(v.z); b.y = __float2half_rn(v.w);
    ((__half2*)dst)[2 * j] = a;
    ((__half2*)dst)[2 * j + 1] = b;
}

// ---------------- grouped fp16 mma.sync GEMM (single-sync multistage) ----------------
// MODE 0: GEMM1+SwiGLU. A = x (gather token). B tile rows interleaved:
//         even = w3(u) col, odd = w1(g) col. Epilogue silu(g)*u -> fp16 h.
//         Block covers 64 h-cols. K=1024.
// MODE 1: GEMM2. A = h (gather slot), B = w2, writes g_pair with routing
//         scale. K=2816.
template <int MODE>
__global__ __launch_bounds__(256, 2) void moe_gemm_kernel() {
    constexpr int K      = (MODE == 0) ? H_DIM : I_DIM;
    constexpr int CHUNKS = K / BKC;

    int e   = blockIdx.z;
    int cnt = g_counts[e];
    int m0  = blockIdx.y * BM;
    if (m0 >= cnt) return;

    const __half* A = (MODE == 0) ? g_x : g_h;
    const __half* B = (MODE == 0) ? g_w31 + (size_t)e * NG1 * H_DIM
                                  : g_w2  + (size_t)e * H_DIM * I_DIM;
    const int* idxA = (MODE == 0) ? &g_tokens[e][0] : &g_slot[e][0];

    extern __shared__ char smem[];
    uint32_t sbase = smem_u32(smem);
    int tid  = threadIdx.x;
    int lane = tid & 31;
    int wid  = tid >> 5;
    int wm   = (wid & 1) * 64;      // warp M offset
    int wn   = (wid >> 1) * 32;     // warp N offset (B-row space)

    // ---- loader mapping: thread -> rows row0+32r, 16B-unit col16 ----
    int col16 = tid & 7;
    int row0  = tid >> 3;
    uint32_t sw[4];
    const __half *aP[4], *bP[4];
    uint32_t asz[4];
#pragma unroll
    for (int r = 0; r < 4; r++) {
        int rt = row0 + 32 * r;
        uint32_t off = rt * 128 + col16 * 16;
        sw[r] = off ^ ((off >> 3) & 0x70);
        int mrow = m0 + rt;
        if (mrow < cnt) {
            size_t rg = (size_t)idxA[mrow];
            aP[r] = A + rg * K + col16 * 8;
            asz[r] = 16;
        } else {
            aP[r] = A; asz[r] = 0;   // zero-fill
        }
        size_t brow;
        if (MODE == 0) {
            int lc = blockIdx.x * 64 + (rt >> 1);                  // logical h col
            brow = (rt & 1) ? (size_t)(I_DIM + lc) : (size_t)lc;   // odd=w1(g), even=w3(u)
        } else {
            brow = (size_t)(blockIdx.x * 128 + rt);
        }
        bP[r] = B + brow * K + col16 * 8;
    }

    auto prefetch = [&](int c, int stg) {
        uint32_t st = sbase + (uint32_t)stg * STAGE_BYTES;
        int k0 = c * BKC;
#pragma unroll
        for (int r = 0; r < 4; r++) {
            cp16(st + OFF_A + sw[r], aP[r] + k0, asz[r]);
            cp16(st + OFF_B + sw[r], bP[r] + k0, 16);
        }
        CP_COMMIT();
    };

    // ---- ldmatrix address precompute ----
    int kh = lane >> 4;
    uint32_t rowOffA[4], rxA[4];
#pragma unroll
    for (int mi = 0; mi < 4; mi++) {
        int ra = wm + mi * 16 + (lane & 15);
        rowOffA[mi] = (uint32_t)ra * 128;
        rxA[mi] = ra & 7;
    }
    uint32_t rowOffB[2], rxB[2];
#pragma unroll
    for (int g = 0; g < 2; g++) {
        int rb = wn + g * 16 + (lane & 15);
        rowOffB[g] = (uint32_t)rb * 128;
        rxB[g] = rb & 7;
    }

    float acc[4][4][4] = {};   // [mi][g*2+s][4]

    // single-sync multistage prologue: fill 2 of 3 stages
    prefetch(0, 0);
    prefetch(1, 1);

    int stg = 0;
    for (int c = 0; c < CHUNKS; c++) {
        if (c + 1 < CHUNKS) { CP_WAIT1(); } else { CP_WAIT0(); }
        __syncthreads();                        // ONE barrier per chunk
        // prefetch into the slot consumed at iteration c-1 (safe: barrier above
        // proves all warps finished reading it); keeps 2 groups in flight.
        if (c + 2 < CHUNKS) {
            int ps = stg + 2; if (ps >= NSTAGE) ps -= NSTAGE;
            prefetch(c + 2, ps);
        }
        uint32_t st = sbase + (uint32_t)stg * STAGE_BYTES;

#pragma unroll
        for (int ks = 0; ks < 4; ks++) {
            uint32_t ub = (uint32_t)(ks * 2 + kh);
            uint32_t af[4][4], bf[2][4];
#pragma unroll
            for (int g = 0; g < 2; g++)
                LDSM_X4(bf[g], st + OFF_B + rowOffB[g] + ((ub ^ rxB[g]) << 4));
#pragma unroll
            for (int mi = 0; mi < 4; mi++)
                LDSM_X4(af[mi], st + OFF_A + rowOffA[mi] + ((ub ^ rxA[mi]) << 4));
            // 16 independent MMAs
#pragma unroll
            for (int mi = 0; mi < 4; mi++)
#pragma unroll
                for (int g = 0; g < 2; g++)
#pragma unroll
                    for (int s = 0; s < 2; s++)
                        mma16816(acc[mi][g * 2 + s], af[mi], bf[g][0 + s], bf[g][2 + s]);
        }
        stg++; if (stg >= NSTAGE) stg = 0;
    }

    // ---- epilogue ----
#pragma unroll
    for (int mi = 0; mi < 4; mi++) {
        int r0 = m0 + wm + mi * 16 + (lane >> 2);
        int r1 = r0 + 8;
        bool v0 = r0 < cnt, v1 = r1 < cnt;
        int  s0 = v0 ? g_slot[e][r0] : 0;
        int  s1 = v1 ? g_slot[e][r1] : 0;
        if (MODE == 0) {
            // acc[mi][j]: c0=u(r0), c1=g(r0), c2=u(r1), c3=g(r1) for h col hc
#pragma unroll
            for (int j = 0; j < 4; j++) {
                int hc = blockIdx.x * 64 + (wn >> 1) + j * 4 + (lane & 3);
                if (v0) {
                    float gg = acc[mi][j][1];
                    float hv = acc[mi][j][0] * (gg / (1.f + __expf(-gg)));
                    g_h[(size_t)s0 * I_DIM + hc] = __float2half_rn(hv);
                }
                if (v1) {
                    float gg = acc[mi][j][3];
                    float hv = acc[mi][j][2] * (gg / (1.f + __expf(-gg)));
                    g_h[(size_t)s1 * I_DIM + hc] = __float2half_rn(hv);
                }
            }
        } else {
            float sc0 = v0 ? g_scales[e][r0] : 0.f;
            float sc1 = v1 ? g_scales[e][r1] : 0.f;
            float* p0 = g_pair + (size_t)s0 * H_DIM;
            float* p1 = g_pair + (size_t)s1 * H_DIM;
#pragma unroll
            for (int j = 0; j < 4; j++) {
                int cc = blockIdx.x * 128 + wn + j * 8 + (lane & 3) * 2;
                if (v0) {
                    float2 w = make_float2(acc[mi][j][0] * sc0, acc[mi][j][1] * sc0);
                    *(float2*)(p0 + cc) = w;
                }
                if (v1) {
                    float2 w = make_float2(acc[mi][j][2] * sc1, acc[mi][j][3] * sc1);
                    *(float2*)(p1 + cc) = w;
                }
            }
        }
    }
}

// out[t] = pair[2t] + pair[2t+1]
__global__ void combine_kernel(float* __restrict__ out) {
    int idx = blockIdx.x * blockDim.x + threadIdx.x;
    const int HV = H_DIM / 4;
    if (idx >= T_TOK * HV) return;
    int t = idx / HV;
    int c = idx - t * HV;
    const float4* p = (const float4*)g_pair;
    float4 a = p[(size_t)(2 * t) * HV + c];
    float4 b = p[(size_t)(2 * t + 1) * HV + c];
    ((float4*)out)[idx] = make_float4(a.x + b.x, a.y + b.y, a.z + b.z, a.w + b.w);
}

extern "C" void kernel_launch(void* const* d_in, const int* in_sizes, int n_in,
                              void* d_out, int out_size) {
    const float* x      = (const float*)d_in[0];
    const float* logits = (const float*)d_in[1];
    const float* w3w1   = (const float*)d_in[2];
    const float* w2     = (const float*)d_in[3];
    float* out = (float*)d_out;

    cudaFuncSetAttribute(moe_gemm_kernel<0>, cudaFuncAttributeMaxDynamicSharedMemorySize, SMEM_DYN);
    cudaFuncSetAttribute(moe_gemm_kernel<1>, cudaFuncAttributeMaxDynamicSharedMemorySize, SMEM_DYN);

    zero_counts_kernel<<<1, 32>>>();
    router_kernel<<<(T_TOK + 255) / 256, 256>>>(logits);

    int n4tot = N4X + N4W1 + N4W2;
    cvt_all_kernel<<<(n4tot + 255) / 256, 256>>>(x, w3w1, w2);

    dim3 blk(256);
    dim3 g1(I_DIM / 64, T_TOK / BM, N_EXP);  // 44 x 32 x 8 (64 h-cols per block)
    moe_gemm_kernel<0><<<g1, blk, SMEM_DYN>>>();

    dim3 g2(H_DIM / 128, T_TOK / BM, N_EXP); // 8 x 32 x 8
    moe_gemm_kernel<1><<<g2, blk, SMEM_DYN>>>();

    combine_kernel<<<(T_TOK * (H_DIM / 4) + 255) / 256, 256>>>(out);
}